// round 2
// baseline (speedup 1.0000x reference)
#include <cuda_runtime.h>

#define N_USERS 10000
#define N_ITEMS 40000
#define N_TOT   50000
#define HID     64
#define NCOL    128      // two embedding sets side-by-side
#define NNZ_    2000000
#define BATCH   8192
#define HOPS    3

// ---------------- scratch (allocation-free rule: __device__ globals) --------
__device__ float g_Hs [N_USERS * NCOL];
__device__ float g_Hs2[N_USERS * NCOL];
__device__ float g_accS[N_USERS * NCOL];
__device__ float g_Ha [N_TOT * NCOL];
__device__ float g_Ha2[N_TOT * NCOL];
__device__ float g_accA[N_TOT * NCOL];

// vector reduction (sm_90+): one LTS op per 16 bytes instead of 4 scalar atomics
__device__ __forceinline__ void red_add_v4(float* addr, float x, float y, float z, float w) {
    asm volatile("red.global.add.v4.f32 [%0], {%1, %2, %3, %4};"
                 :: "l"(addr), "f"(x), "f"(y), "f"(z), "f"(w) : "memory");
}

// ---------------- init kernels ---------------------------------------------
__global__ void init_social(const float* __restrict__ ue, const float* __restrict__ u1,
                            float* __restrict__ H, float* __restrict__ acc) {
    int idx = blockIdx.x * blockDim.x + threadIdx.x;
    if (idx >= N_USERS * HID) return;
    int u = idx >> 6, c = idx & 63;
    float a = ue[idx], b = u1[idx];
    H[u * NCOL + c] = a;        H[u * NCOL + 64 + c] = b;
    acc[u * NCOL + c] = a;      acc[u * NCOL + 64 + c] = b;
}

__global__ void init_ui(const float* __restrict__ ue, const float* __restrict__ ie,
                        const float* __restrict__ u2, const float* __restrict__ i2,
                        float* __restrict__ H, float* __restrict__ acc) {
    int idx = blockIdx.x * blockDim.x + threadIdx.x;
    if (idx >= N_TOT * HID) return;
    int n = idx >> 6, c = idx & 63;
    float a, b;
    if (n < N_USERS) { a = ue[n * 64 + c];              b = u2[n * 64 + c]; }
    else             { int m = n - N_USERS; a = ie[m * 64 + c]; b = i2[m * 64 + c]; }
    H[n * NCOL + c] = a;        H[n * NCOL + 64 + c] = b;
    acc[n * NCOL + c] = a;      acc[n * NCOL + 64 + c] = b;
}

// ---------------- dense SGEMM: C[M,128] (+)= A[M,K] * B[K,128], split-K -----
#define BM 128
#define BN 128
#define BK 16
#define TM 8
#define TN 8

__global__ __launch_bounds__(256, 2)
void sgemm_splitk(const float* __restrict__ A, const float* __restrict__ B,
                  float* __restrict__ C, int M, int K)
{
    const int m0 = blockIdx.x * BM;
    const int nsplit = gridDim.y;
    const int kLen = (K + nsplit - 1) / nsplit;           // 2500 (mult of 4)
    const int k0 = blockIdx.y * kLen;
    const int k1 = min(K, k0 + kLen);

    __shared__ float As[2][BK][BM + 4];   // transposed + padded
    __shared__ float Bs[2][BK][BN];

    const int tid = threadIdx.x;
    const int ty = tid >> 4, tx = tid & 15;

    float acc[TM][TN];
#pragma unroll
    for (int i = 0; i < TM; i++)
#pragma unroll
        for (int j = 0; j < TN; j++) acc[i][j] = 0.f;

    // load index split: A tile 128x16 -> 512 float4 (2/thread), B tile 16x128 likewise
    const int arow0 = tid >> 2;               // 0..63 (+64)
    const int akc   = (tid & 3) * 4;          // 0,4,8,12
    const int brow0 = tid >> 5;               // 0..7 (+8)
    const int bcol  = (tid & 31) * 4;

    const int ntiles = (k1 - k0 + BK - 1) / BK;

    float4 pa[2], pb[2];

#define LOAD_REGS(T)                                                            \
    {                                                                           \
        int kk = k0 + (T) * BK;                                                 \
        _Pragma("unroll")                                                       \
        for (int i = 0; i < 2; i++) {                                           \
            int gm = m0 + arow0 + i * 64;                                       \
            int gk = kk + akc;                                                  \
            pa[i] = make_float4(0.f, 0.f, 0.f, 0.f);                            \
            if (gm < M && gk < k1) pa[i] = *(const float4*)(A + (size_t)gm * K + gk); \
        }                                                                       \
        _Pragma("unroll")                                                       \
        for (int i = 0; i < 2; i++) {                                           \
            int gk = kk + brow0 + i * 8;                                        \
            pb[i] = make_float4(0.f, 0.f, 0.f, 0.f);                            \
            if (gk < k1) pb[i] = *(const float4*)(B + (size_t)gk * BN + bcol);  \
        }                                                                       \
    }

#define STORE_SMEM(BUF)                                                         \
    {                                                                           \
        _Pragma("unroll")                                                       \
        for (int i = 0; i < 2; i++) {                                           \
            int row = arow0 + i * 64;                                           \
            As[BUF][akc + 0][row] = pa[i].x;                                    \
            As[BUF][akc + 1][row] = pa[i].y;                                    \
            As[BUF][akc + 2][row] = pa[i].z;                                    \
            As[BUF][akc + 3][row] = pa[i].w;                                    \
        }                                                                       \
        _Pragma("unroll")                                                       \
        for (int i = 0; i < 2; i++)                                             \
            *(float4*)&Bs[BUF][brow0 + i * 8][bcol] = pb[i];                    \
    }

    LOAD_REGS(0)
    STORE_SMEM(0)
    __syncthreads();

    for (int t = 0; t < ntiles; t++) {
        int buf = t & 1;
        if (t + 1 < ntiles) LOAD_REGS(t + 1)

#pragma unroll
        for (int k = 0; k < BK; k++) {
            float a[TM], b[TN];
#pragma unroll
            for (int i = 0; i < TM; i++) a[i] = As[buf][k][ty * TM + i];
#pragma unroll
            for (int j = 0; j < TN; j++) b[j] = Bs[buf][k][tx * TN + j];
#pragma unroll
            for (int i = 0; i < TM; i++)
#pragma unroll
                for (int j = 0; j < TN; j++)
                    acc[i][j] += a[i] * b[j];
        }

        if (t + 1 < ntiles) STORE_SMEM(buf ^ 1)
        __syncthreads();
    }

    // split-K accumulate into zeroed C via vector reduction
#pragma unroll
    for (int i = 0; i < TM; i++) {
        int gm = m0 + ty * TM + i;
        if (gm < M) {
#pragma unroll
            for (int j = 0; j < TN; j += 4)
                red_add_v4(C + (size_t)gm * BN + tx * TN + j,
                           acc[i][j], acc[i][j + 1], acc[i][j + 2], acc[i][j + 3]);
        }
    }
}

// ---------------- sparse SpMM: one warp per edge, 128 cols ------------------
__global__ void spmm_kernel(const int* __restrict__ rows, const int* __restrict__ cols,
                            const float* __restrict__ vals,
                            const float* __restrict__ H, float* __restrict__ Hout, int nnz)
{
    int warp = (blockIdx.x * blockDim.x + threadIdx.x) >> 5;
    int lane = threadIdx.x & 31;
    if (warp >= nnz) return;
    int r = rows[warp];
    int c = cols[warp];
    float v = vals[warp];
    const float4 h = *(const float4*)(H + (size_t)c * NCOL + lane * 4);
    red_add_v4(Hout + (size_t)r * NCOL + lane * 4, h.x * v, h.y * v, h.z * v, h.w * v);
}

// ---------------- acc += h ---------------------------------------------------
__global__ void add_acc(float4* __restrict__ acc, const float4* __restrict__ h, int n4) {
    int i = blockIdx.x * blockDim.x + threadIdx.x;
    if (i < n4) {
        float4 a = acc[i], b = h[i];
        a.x += b.x; a.y += b.y; a.z += b.z; a.w += b.w;
        acc[i] = a;
    }
}

// ---------------- finalize: all 11 output segments ---------------------------
__global__ void finalize(const float* __restrict__ accS, const float* __restrict__ accA,
                         const float* __restrict__ item1,
                         const int* __restrict__ users, const int* __restrict__ pos,
                         const int* __restrict__ neg, float* __restrict__ out)
{
    const int TOTROWS = 9 * BATCH + 2 * N_USERS;
    int gid = blockIdx.x * blockDim.x + threadIdx.x;
    if (gid >= TOTROWS * 64) return;
    int row = gid >> 6, c = gid & 63;
    float v;
    if (row < BATCH) {                                  // all_user[users]
        int u = users[row];
        v = (accS[u * NCOL + c] + accA[u * NCOL + c]) * 0.125f;
    } else if (row < 2 * BATCH) {                       // all_item[pos]
        int i = pos[row - BATCH];
        v = accA[(size_t)(N_USERS + i) * NCOL + c] * 0.25f;
    } else if (row < 3 * BATCH) {                       // all_item[neg]
        int i = neg[row - 2 * BATCH];
        v = accA[(size_t)(N_USERS + i) * NCOL + c] * 0.25f;
    } else if (row < 3 * BATCH + N_USERS) {             // all_user_S
        int u = row - 3 * BATCH;
        v = accS[u * NCOL + c] * 0.25f;
    } else if (row < 3 * BATCH + 2 * N_USERS) {         // all_user_A
        int u = row - 3 * BATCH - N_USERS;
        v = accA[u * NCOL + c] * 0.25f;
    } else if (row < 4 * BATCH + 2 * N_USERS) {         // all_user_social[users]
        int u = users[row - 3 * BATCH - 2 * N_USERS];
        v = accS[u * NCOL + 64 + c] * 0.25f;
    } else if (row < 5 * BATCH + 2 * N_USERS) {         // all_item_social[pos] = item1[pos]
        int i = pos[row - 4 * BATCH - 2 * N_USERS];
        v = item1[(size_t)i * 64 + c];
    } else if (row < 6 * BATCH + 2 * N_USERS) {         // all_item_social[neg]
        int i = neg[row - 5 * BATCH - 2 * N_USERS];
        v = item1[(size_t)i * 64 + c];
    } else if (row < 7 * BATCH + 2 * N_USERS) {         // all_user_rating[users]
        int u = users[row - 6 * BATCH - 2 * N_USERS];
        v = accA[u * NCOL + 64 + c] * 0.25f;
    } else if (row < 8 * BATCH + 2 * N_USERS) {         // all_item_rating[pos]
        int i = pos[row - 7 * BATCH - 2 * N_USERS];
        v = accA[(size_t)(N_USERS + i) * NCOL + 64 + c] * 0.25f;
    } else {                                            // all_item_rating[neg]
        int i = neg[row - 8 * BATCH - 2 * N_USERS];
        v = accA[(size_t)(N_USERS + i) * NCOL + 64 + c] * 0.25f;
    }
    out[gid] = v;
}

// ---------------- launch ----------------------------------------------------
extern "C" void kernel_launch(void* const* d_in, const int* in_sizes, int n_in,
                              void* d_out, int out_size)
{
    const int*   users = (const int*)d_in[0];
    const int*   pos   = (const int*)d_in[1];
    const int*   neg   = (const int*)d_in[2];
    const float* ue    = (const float*)d_in[3];
    const float* ie    = (const float*)d_in[4];
    const float* u1    = (const float*)d_in[5];
    const float* i1    = (const float*)d_in[6];
    const float* u2    = (const float*)d_in[7];
    const float* i2    = (const float*)d_in[8];
    const float* S     = (const float*)d_in[9];
    const int*   arows = (const int*)d_in[10];
    const int*   acols = (const int*)d_in[11];
    const float* avals = (const float*)d_in[12];
    float* out = (float*)d_out;

    float *Hs, *Hs2, *aS, *Ha, *Ha2, *aA;
    cudaGetSymbolAddress((void**)&Hs,  g_Hs);
    cudaGetSymbolAddress((void**)&Hs2, g_Hs2);
    cudaGetSymbolAddress((void**)&aS,  g_accS);
    cudaGetSymbolAddress((void**)&Ha,  g_Ha);
    cudaGetSymbolAddress((void**)&Ha2, g_Ha2);
    cudaGetSymbolAddress((void**)&aA,  g_accA);

    init_social<<<(N_USERS * HID + 255) / 256, 256>>>(ue, u1, Hs, aS);
    init_ui<<<(N_TOT * HID + 255) / 256, 256>>>(ue, ie, u2, i2, Ha, aA);

    // social: 3 hops of fused [10000,128] dense GEMM
    {
        float* cur = Hs; float* nxt = Hs2;
        for (int h = 0; h < HOPS; h++) {
            cudaMemsetAsync(nxt, 0, (size_t)N_USERS * NCOL * sizeof(float));
            dim3 grid((N_USERS + BM - 1) / BM, 4);   // split-K=4
            sgemm_splitk<<<grid, 256>>>(S, cur, nxt, N_USERS, N_USERS);
            add_acc<<<(N_USERS * NCOL / 4 + 255) / 256, 256>>>(
                (float4*)aS, (const float4*)nxt, N_USERS * NCOL / 4);
            float* t = cur; cur = nxt; nxt = t;
        }
    }

    // user-item: 3 hops of fused sparse SpMM over 2M edges, 128 cols
    {
        float* cur = Ha; float* nxt = Ha2;
        for (int h = 0; h < HOPS; h++) {
            cudaMemsetAsync(nxt, 0, (size_t)N_TOT * NCOL * sizeof(float));
            spmm_kernel<<<(NNZ_ + 7) / 8, 256>>>(arows, acols, avals, cur, nxt, NNZ_);
            add_acc<<<(N_TOT * NCOL / 4 + 255) / 256, 256>>>(
                (float4*)aA, (const float4*)nxt, N_TOT * NCOL / 4);
            float* t = cur; cur = nxt; nxt = t;
        }
    }

    const int totrows = 9 * BATCH + 2 * N_USERS;
    finalize<<<(totrows * 64 + 255) / 256, 256>>>(aS, aA, i1, users, pos, neg, out);
}

// round 4
// speedup vs baseline: 1.4206x; 1.4206x over previous
#include <cuda_runtime.h>
#include <cuda_bf16.h>
#include <cstdint>

#define N_USERS 10000
#define N_ITEMS 40000
#define N_TOT   50000
#define HID     64
#define NCOL    128
#define NNZ_    2000000
#define BATCH   8192
#define HOPS    3

// GEMM padding
#define MPAD    10112          // 79 * 128
#define KPAD    10112          // 316 * 32
#define KSPLIT  5056           // KPAD / 2
#define KCH2    158            // KSPLIT / 32
#define NITER   474            // 3 phases * KCH2

// smem stage: A 128 rows x 80B + B 128 rows x 80B
#define ROWB    80
#define ASZ     (128 * ROWB)
#define STAGE   (2 * ASZ)

// ---------------- scratch (__device__ globals; zero-init => padding stays 0) --
__device__ __nv_bfloat16 g_Ahi[(size_t)MPAD * KPAD];
__device__ __nv_bfloat16 g_Alo[(size_t)MPAD * KPAD];
__device__ __nv_bfloat16 g_Bhi[(size_t)128 * KPAD];
__device__ __nv_bfloat16 g_Blo[(size_t)128 * KPAD];
__device__ float g_C1[(size_t)MPAD * NCOL];
__device__ float g_C2[(size_t)MPAD * NCOL];
__device__ float g_Hs [N_USERS * NCOL];
__device__ float g_accS[N_USERS * NCOL];
__device__ float g_Ha [N_TOT * NCOL];
__device__ float g_Ha2[N_TOT * NCOL];
__device__ float g_accA[N_TOT * NCOL];

// ---------------- PTX helpers ------------------------------------------------
__device__ __forceinline__ void red_add_v4(float* addr, float x, float y, float z, float w) {
    asm volatile("red.global.add.v4.f32 [%0], {%1, %2, %3, %4};"
                 :: "l"(addr), "f"(x), "f"(y), "f"(z), "f"(w) : "memory");
}
__device__ __forceinline__ void red_add_v2(float* addr, float x, float y) {
    asm volatile("red.global.add.v2.f32 [%0], {%1, %2};"
                 :: "l"(addr), "f"(x), "f"(y) : "memory");
}

__device__ __forceinline__ uint32_t smem_u32(const void* p) {
    uint32_t a;
    asm("{ .reg .u64 t; cvta.to.shared.u64 t, %1; cvt.u32.u64 %0, t; }" : "=r"(a) : "l"(p));
    return a;
}

#define CPASYNC(dst, src) \
    asm volatile("cp.async.cg.shared.global [%0], [%1], 16;" :: "r"(dst), "l"(src) : "memory")
#define CPCOMMIT() asm volatile("cp.async.commit_group;" ::: "memory")
#define CPWAIT(n)  asm volatile("cp.async.wait_group %0;" :: "n"(n) : "memory")

#define LDSM4(r0, r1, r2, r3, addr)                                              \
    asm volatile("ldmatrix.sync.aligned.m8n8.x4.shared.b16 {%0,%1,%2,%3}, [%4];" \
                 : "=r"(r0), "=r"(r1), "=r"(r2), "=r"(r3) : "r"(addr))

#define MMA_BF16(d, a, b)                                                        \
    asm volatile("mma.sync.aligned.m16n8k16.row.col.f32.bf16.bf16.f32 "          \
                 "{%0,%1,%2,%3}, {%4,%5,%6,%7}, {%8,%9}, {%0,%1,%2,%3};"         \
                 : "+f"((d)[0]), "+f"((d)[1]), "+f"((d)[2]), "+f"((d)[3])        \
                 : "r"((a)[0]), "r"((a)[1]), "r"((a)[2]), "r"((a)[3]),           \
                   "r"((b)[0]), "r"((b)[1]))

// ---------------- split conversions ------------------------------------------
__global__ void conv_S(const float4* __restrict__ S4,
                       __nv_bfloat16* __restrict__ Ahi, __nv_bfloat16* __restrict__ Alo)
{
    int i = blockIdx.x * blockDim.x + threadIdx.x;
    if (i >= N_USERS * 2500) return;
    int m = i / 2500, k4 = i - m * 2500;
    float4 v = S4[i];
    size_t o = (size_t)m * KPAD + (size_t)k4 * 4;
    __nv_bfloat16 h0 = __float2bfloat16(v.x), h1 = __float2bfloat16(v.y);
    __nv_bfloat16 h2 = __float2bfloat16(v.z), h3 = __float2bfloat16(v.w);
    __nv_bfloat16 l0 = __float2bfloat16(v.x - __bfloat162float(h0));
    __nv_bfloat16 l1 = __float2bfloat16(v.y - __bfloat162float(h1));
    __nv_bfloat16 l2 = __float2bfloat16(v.z - __bfloat162float(h2));
    __nv_bfloat16 l3 = __float2bfloat16(v.w - __bfloat162float(h3));
    uint32_t* ph = reinterpret_cast<uint32_t*>(Ahi + o);
    uint32_t* pl = reinterpret_cast<uint32_t*>(Alo + o);
    ph[0] = (uint32_t)__bfloat16_as_ushort(h0) | ((uint32_t)__bfloat16_as_ushort(h1) << 16);
    ph[1] = (uint32_t)__bfloat16_as_ushort(h2) | ((uint32_t)__bfloat16_as_ushort(h3) << 16);
    pl[0] = (uint32_t)__bfloat16_as_ushort(l0) | ((uint32_t)__bfloat16_as_ushort(l1) << 16);
    pl[1] = (uint32_t)__bfloat16_as_ushort(l2) | ((uint32_t)__bfloat16_as_ushort(l3) << 16);
}

// h [N_USERS x 128] f32  ->  Bt_hi/Bt_lo [128 x KPAD] bf16 (transposed split)
__global__ void conv_Bt(const float* __restrict__ h,
                        __nv_bfloat16* __restrict__ Bhi, __nv_bfloat16* __restrict__ Blo)
{
    __shared__ float t[32][33];
    int k0 = blockIdx.x * 32;
    int n0 = blockIdx.y * 32;
    int tx = threadIdx.x, ty = threadIdx.y;   // 32 x 8
#pragma unroll
    for (int r = 0; r < 4; r++) {
        int k = k0 + ty + r * 8;
        if (k < N_USERS) t[ty + r * 8][tx] = h[(size_t)k * NCOL + n0 + tx];
    }
    __syncthreads();
#pragma unroll
    for (int r = 0; r < 4; r++) {
        int n = n0 + ty + r * 8;
        int k = k0 + tx;
        if (k < N_USERS) {
            float v = t[tx][ty + r * 8];
            __nv_bfloat16 hi = __float2bfloat16(v);
            __nv_bfloat16 lo = __float2bfloat16(v - __bfloat162float(hi));
            Bhi[(size_t)n * KPAD + k] = hi;
            Blo[(size_t)n * KPAD + k] = lo;
        }
    }
}

// ---------------- mma.sync bf16 GEMM: C[MPAD,128] += 3-term split ------------
__global__ __launch_bounds__(256)
void gemm_social(const __nv_bfloat16* __restrict__ Ahi, const __nv_bfloat16* __restrict__ Alo,
                 const __nv_bfloat16* __restrict__ Bhi, const __nv_bfloat16* __restrict__ Blo,
                 float* __restrict__ C)
{
    __shared__ __align__(16) char smem[2 * STAGE];
    const uint32_t sbase = smem_u32(smem);
    const int tid = threadIdx.x;
    const int wid = tid >> 5, lane = tid & 31;
    const int wm = (wid >> 2) * 64;        // warp M offset in tile
    const int wn = (wid & 3) * 32;         // warp N offset
    const int m0 = blockIdx.x * 128;
    const size_t kbase = (size_t)blockIdx.y * KSPLIT;

    float d[4][4][4];
#pragma unroll
    for (int a = 0; a < 4; a++)
#pragma unroll
        for (int b = 0; b < 4; b++)
#pragma unroll
            for (int c = 0; c < 4; c++) d[a][b][c] = 0.f;

    // per-thread load slots: 512 A chunks + 512 B chunks of 16B per stage
    const int lr  = tid >> 2;          // 0..63 base row (x2)
    const int lc  = tid & 3;           // 16B chunk within 64B row segment

    // ldmatrix lane addressing (within warp)
    const int arow = (lane & 7) + ((lane >> 3) & 1) * 8;
    const int acol = (lane >> 4) * 16;                 // +8 k -> +16B
    const int brow = ((lane >> 4) * 8) + (lane & 7);
    const int bcol = ((lane >> 3) & 1) * 16;

#define PREFETCH(IT)                                                              \
    {                                                                             \
        int ph = (IT) / KCH2;                                                     \
        int kc = (IT) - ph * KCH2;                                                \
        const __nv_bfloat16* Ap = (ph == 2) ? Alo : Ahi;                          \
        const __nv_bfloat16* Bp = (ph == 1) ? Blo : Bhi;                          \
        size_t koff = kbase + (size_t)kc * 32;                                    \
        uint32_t dA = sbase + ((IT) & 1) * STAGE;                                 \
        uint32_t dB = dA + ASZ;                                                   \
        _Pragma("unroll")                                                         \
        for (int j = 0; j < 2; j++) {                                             \
            int r = lr + j * 64;                                                  \
            CPASYNC(dA + r * ROWB + lc * 16,                                      \
                    Ap + (size_t)(m0 + r) * KPAD + koff + lc * 8);                \
            CPASYNC(dB + r * ROWB + lc * 16,                                      \
                    Bp + (size_t)r * KPAD + koff + lc * 8);                       \
        }                                                                         \
    }

    PREFETCH(0)
    CPCOMMIT();

#pragma unroll 1
    for (int it = 0; it < NITER; it++) {
        if (it + 1 < NITER) {
            PREFETCH(it + 1)
            CPCOMMIT();
            CPWAIT(1);
        } else {
            CPWAIT(0);
        }
        __syncthreads();

        uint32_t sA = sbase + (it & 1) * STAGE;
        uint32_t sB = sA + ASZ;

#pragma unroll
        for (int kk = 0; kk < 2; kk++) {           // two k16 steps in BK=32
            uint32_t a[4][4], b[4][2];
#pragma unroll
            for (int mt = 0; mt < 4; mt++) {
                uint32_t addr = sA + (wm + mt * 16 + arow) * ROWB + kk * 32 + acol;
                LDSM4(a[mt][0], a[mt][1], a[mt][2], a[mt][3], addr);
            }
#pragma unroll
            for (int bt = 0; bt < 2; bt++) {
                uint32_t addr = sB + (wn + bt * 16 + brow) * ROWB + kk * 32 + bcol;
                LDSM4(b[bt * 2][0], b[bt * 2][1], b[bt * 2 + 1][0], b[bt * 2 + 1][1], addr);
            }
#pragma unroll
            for (int mt = 0; mt < 4; mt++)
#pragma unroll
                for (int nt = 0; nt < 4; nt++)
                    MMA_BF16(d[mt][nt], a[mt], b[nt]);
        }
        __syncthreads();
    }

    // epilogue: red.global.add.v2 into zeroed C (split-K accumulate)
    const int rbase = m0 + wm + (lane >> 2);
    const int cbase = wn + 2 * (lane & 3);
#pragma unroll
    for (int mt = 0; mt < 4; mt++) {
        int r0 = rbase + mt * 16;
#pragma unroll
        for (int nt = 0; nt < 4; nt++) {
            int c = cbase + nt * 8;
            red_add_v2(C + (size_t)r0 * NCOL + c,       d[mt][nt][0], d[mt][nt][1]);
            red_add_v2(C + (size_t)(r0 + 8) * NCOL + c, d[mt][nt][2], d[mt][nt][3]);
        }
    }
}

// ---------------- init kernels ----------------------------------------------
__global__ void init_social(const float* __restrict__ ue, const float* __restrict__ u1,
                            float* __restrict__ H, float* __restrict__ acc) {
    int idx = blockIdx.x * blockDim.x + threadIdx.x;
    if (idx >= N_USERS * HID) return;
    int u = idx >> 6, c = idx & 63;
    float a = ue[idx], b = u1[idx];
    H[u * NCOL + c] = a;        H[u * NCOL + 64 + c] = b;
    acc[u * NCOL + c] = a;      acc[u * NCOL + 64 + c] = b;
}

__global__ void init_ui(const float* __restrict__ ue, const float* __restrict__ ie,
                        const float* __restrict__ u2, const float* __restrict__ i2,
                        float* __restrict__ H, float* __restrict__ acc) {
    int idx = blockIdx.x * blockDim.x + threadIdx.x;
    if (idx >= N_TOT * HID) return;
    int n = idx >> 6, c = idx & 63;
    float a, b;
    if (n < N_USERS) { a = ue[n * 64 + c];              b = u2[n * 64 + c]; }
    else             { int m = n - N_USERS; a = ie[(size_t)m * 64 + c]; b = i2[(size_t)m * 64 + c]; }
    H[n * NCOL + c] = a;        H[n * NCOL + 64 + c] = b;
    acc[n * NCOL + c] = a;      acc[n * NCOL + 64 + c] = b;
}

// ---------------- sparse SpMM: one warp per edge ----------------------------
__global__ void spmm_kernel(const int* __restrict__ rows, const int* __restrict__ cols,
                            const float* __restrict__ vals,
                            const float* __restrict__ H, float* __restrict__ Hout, int nnz)
{
    int warp = (blockIdx.x * blockDim.x + threadIdx.x) >> 5;
    int lane = threadIdx.x & 31;
    if (warp >= nnz) return;
    int r = rows[warp];
    int c = cols[warp];
    float v = vals[warp];
    const float4 h = *(const float4*)(H + (size_t)c * NCOL + lane * 4);
    red_add_v4(Hout + (size_t)r * NCOL + lane * 4, h.x * v, h.y * v, h.z * v, h.w * v);
}

__global__ void add_acc(float4* __restrict__ acc, const float4* __restrict__ h, int n4) {
    int i = blockIdx.x * blockDim.x + threadIdx.x;
    if (i < n4) {
        float4 a = acc[i], b = h[i];
        a.x += b.x; a.y += b.y; a.z += b.z; a.w += b.w;
        acc[i] = a;
    }
}

// ---------------- finalize ---------------------------------------------------
__global__ void finalize(const float* __restrict__ accS, const float* __restrict__ accA,
                         const float* __restrict__ item1,
                         const int* __restrict__ users, const int* __restrict__ pos,
                         const int* __restrict__ neg, float* __restrict__ out)
{
    const int TOTROWS = 9 * BATCH + 2 * N_USERS;
    int gid = blockIdx.x * blockDim.x + threadIdx.x;
    if (gid >= TOTROWS * 64) return;
    int row = gid >> 6, c = gid & 63;
    float v;
    if (row < BATCH) {
        int u = users[row];
        v = (accS[u * NCOL + c] + accA[u * NCOL + c]) * 0.125f;
    } else if (row < 2 * BATCH) {
        int i = pos[row - BATCH];
        v = accA[(size_t)(N_USERS + i) * NCOL + c] * 0.25f;
    } else if (row < 3 * BATCH) {
        int i = neg[row - 2 * BATCH];
        v = accA[(size_t)(N_USERS + i) * NCOL + c] * 0.25f;
    } else if (row < 3 * BATCH + N_USERS) {
        int u = row - 3 * BATCH;
        v = accS[u * NCOL + c] * 0.25f;
    } else if (row < 3 * BATCH + 2 * N_USERS) {
        int u = row - 3 * BATCH - N_USERS;
        v = accA[u * NCOL + c] * 0.25f;
    } else if (row < 4 * BATCH + 2 * N_USERS) {
        int u = users[row - 3 * BATCH - 2 * N_USERS];
        v = accS[u * NCOL + 64 + c] * 0.25f;
    } else if (row < 5 * BATCH + 2 * N_USERS) {
        int i = pos[row - 4 * BATCH - 2 * N_USERS];
        v = item1[(size_t)i * 64 + c];
    } else if (row < 6 * BATCH + 2 * N_USERS) {
        int i = neg[row - 5 * BATCH - 2 * N_USERS];
        v = item1[(size_t)i * 64 + c];
    } else if (row < 7 * BATCH + 2 * N_USERS) {
        int u = users[row - 6 * BATCH - 2 * N_USERS];
        v = accA[u * NCOL + 64 + c] * 0.25f;
    } else if (row < 8 * BATCH + 2 * N_USERS) {
        int i = pos[row - 7 * BATCH - 2 * N_USERS];
        v = accA[(size_t)(N_USERS + i) * NCOL + 64 + c] * 0.25f;
    } else {
        int i = neg[row - 8 * BATCH - 2 * N_USERS];
        v = accA[(size_t)(N_USERS + i) * NCOL + 64 + c] * 0.25f;
    }
    out[gid] = v;
}

// ---------------- launch ----------------------------------------------------
extern "C" void kernel_launch(void* const* d_in, const int* in_sizes, int n_in,
                              void* d_out, int out_size)
{
    const int*   users = (const int*)d_in[0];
    const int*   pos   = (const int*)d_in[1];
    const int*   neg   = (const int*)d_in[2];
    const float* ue    = (const float*)d_in[3];
    const float* ie    = (const float*)d_in[4];
    const float* u1    = (const float*)d_in[5];
    const float* i1    = (const float*)d_in[6];
    const float* u2    = (const float*)d_in[7];
    const float* i2    = (const float*)d_in[8];
    const float* S     = (const float*)d_in[9];
    const int*   arows = (const int*)d_in[10];
    const int*   acols = (const int*)d_in[11];
    const float* avals = (const float*)d_in[12];
    float* out = (float*)d_out;

    __nv_bfloat16 *Ahi, *Alo, *Bhi, *Blo;
    float *C1, *C2, *Hs, *aS, *Ha, *Ha2, *aA;
    cudaGetSymbolAddress((void**)&Ahi, g_Ahi);
    cudaGetSymbolAddress((void**)&Alo, g_Alo);
    cudaGetSymbolAddress((void**)&Bhi, g_Bhi);
    cudaGetSymbolAddress((void**)&Blo, g_Blo);
    cudaGetSymbolAddress((void**)&C1,  g_C1);
    cudaGetSymbolAddress((void**)&C2,  g_C2);
    cudaGetSymbolAddress((void**)&Hs,  g_Hs);
    cudaGetSymbolAddress((void**)&aS,  g_accS);
    cudaGetSymbolAddress((void**)&Ha,  g_Ha);
    cudaGetSymbolAddress((void**)&Ha2, g_Ha2);
    cudaGetSymbolAddress((void**)&aA,  g_accA);

    init_social<<<(N_USERS * HID + 255) / 256, 256>>>(ue, u1, Hs, aS);
    init_ui<<<(N_TOT * HID + 255) / 256, 256>>>(ue, ie, u2, i2, Ha, aA);

    // one-time split of S into bf16 hi/lo (padded, padding stays zero)
    conv_S<<<(N_USERS * 2500 + 255) / 256, 256>>>((const float4*)S, Ahi, Alo);

    // social: 3 hops of mma.sync split-bf16 GEMM
    {
        float* cur = Hs;
        for (int h = 0; h < HOPS; h++) {
            conv_Bt<<<dim3((N_USERS + 31) / 32, 4), dim3(32, 8)>>>(cur, Bhi, Blo);
            float* nxt = (h & 1) ? C2 : C1;
            cudaMemsetAsync(nxt, 0, (size_t)MPAD * NCOL * sizeof(float));
            gemm_social<<<dim3(79, 2), 256>>>(Ahi, Alo, Bhi, Blo, nxt);
            add_acc<<<(N_USERS * NCOL / 4 + 255) / 256, 256>>>(
                (float4*)aS, (const float4*)nxt, N_USERS * NCOL / 4);
            cur = nxt;
        }
    }

    // user-item: 3 hops of sparse SpMM over 2M edges, 128 cols
    {
        float* cur = Ha; float* nxt = Ha2;
        for (int h = 0; h < HOPS; h++) {
            cudaMemsetAsync(nxt, 0, (size_t)N_TOT * NCOL * sizeof(float));
            spmm_kernel<<<(NNZ_ + 7) / 8, 256>>>(arows, acols, avals, cur, nxt, NNZ_);
            add_acc<<<(N_TOT * NCOL / 4 + 255) / 256, 256>>>(
                (float4*)aA, (const float4*)nxt, N_TOT * NCOL / 4);
            float* t = cur; cur = nxt; nxt = t;
        }
    }

    const int totrows = 9 * BATCH + 2 * N_USERS;
    finalize<<<(totrows * 64 + 255) / 256, 256>>>(aS, aA, i1, users, pos, neg, out);
}